// round 3
// baseline (speedup 1.0000x reference)
#include <cuda_runtime.h>
#include <cuda_bf16.h>
#include <cstdint>
#include <cstring>

// Problem dims
#define BDIM 16384
#define KDIM 4096
#define NDIM 512

// Binarized weight, bf16 {0,1}, [NDIM, KDIM] row-major (K-contiguous). 4 MB.
__device__ __align__(256) __nv_bfloat16 g_wbin[(size_t)NDIM * KDIM];

// ---------------------------------------------------------------------------
// helpers
// ---------------------------------------------------------------------------
__device__ __forceinline__ uint32_t smem_u32(const void* p) {
    uint32_t a;
    asm("{ .reg .u64 t; cvta.to.shared.u64 t, %1; cvt.u32.u64 %0, t; }"
        : "=r"(a) : "l"(p));
    return a;
}

#define SWZ(off) ((uint32_t)(off) ^ ((((uint32_t)(off)) >> 3) & 0x70))

#define LDSM_X4(r0, r1, r2, r3, addr) \
    asm volatile("ldmatrix.sync.aligned.m8n8.x4.shared.b16 {%0,%1,%2,%3}, [%4];" \
        : "=r"(r0), "=r"(r1), "=r"(r2), "=r"(r3) : "r"(addr))

#define MMA16816(d, a, b0, b1) \
    asm volatile("mma.sync.aligned.m16n8k16.row.col.f32.bf16.bf16.f32 " \
        "{%0,%1,%2,%3}, {%4,%5,%6,%7}, {%8,%9}, {%0,%1,%2,%3};" \
        : "+f"((d)[0]), "+f"((d)[1]), "+f"((d)[2]), "+f"((d)[3]) \
        : "r"((a)[0]), "r"((a)[1]), "r"((a)[2]), "r"((a)[3]), "r"(b0), "r"(b1))

#define CP_ASYNC16(dst, src) \
    asm volatile("cp.async.cg.shared.global [%0], [%1], 16;" \
        :: "r"(dst), "l"(src) : "memory")
#define CP_COMMIT()  asm volatile("cp.async.commit_group;" ::: "memory")
#define CP_WAIT1()   asm volatile("cp.async.wait_group 1;" ::: "memory")

#define STS128(addr, a, b, c, d) \
    asm volatile("st.shared.v4.b32 [%0], {%1, %2, %3, %4};" \
        :: "r"(addr), "r"(a), "r"(b), "r"(c), "r"(d) : "memory")

__device__ __forceinline__ uint32_t pack_bf16x2(float lo, float hi) {
    __nv_bfloat162 h = __floats2bfloat162_rn(lo, hi);
    uint32_t r;
    memcpy(&r, &h, 4);
    return r;
}

// ---------------------------------------------------------------------------
// Kernel 1: binarize weight -> bf16 {0,1}. Pure bit select, no float math.
// ---------------------------------------------------------------------------
__global__ void __launch_bounds__(256) binarize_kernel(
    const float* __restrict__ w, const float* __restrict__ u) {
    int i = blockIdx.x * 256 + threadIdx.x;   // 8 elems each
    const float4* w4 = reinterpret_cast<const float4*>(w) + (size_t)i * 2;
    const float4* u4 = reinterpret_cast<const float4*>(u) + (size_t)i * 2;
    float4 wa = w4[0], wb = w4[1];
    float4 ua = u4[0], ub = u4[1];
    // bf16(1.0f) = 0x3F80
    uint32_t o0 = (ua.x < wa.x ? 0x00003F80u : 0u) | (ua.y < wa.y ? 0x3F800000u : 0u);
    uint32_t o1 = (ua.z < wa.z ? 0x00003F80u : 0u) | (ua.w < wa.w ? 0x3F800000u : 0u);
    uint32_t o2 = (ub.x < wb.x ? 0x00003F80u : 0u) | (ub.y < wb.y ? 0x3F800000u : 0u);
    uint32_t o3 = (ub.z < wb.z ? 0x00003F80u : 0u) | (ub.w < wb.w ? 0x3F800000u : 0u);
    reinterpret_cast<uint4*>(g_wbin)[i] = make_uint4(o0, o1, o2, o3);
}

// ---------------------------------------------------------------------------
// Kernel 2: bf16 mma.sync GEMM.
//   out[16384, 512] = xbf16[16384, 4096] @ wbin[512, 4096]^T
//   BM=128, BN=128, BK=64. 512 threads = 16 warps (4 x 4), warp tile 32x32.
//   (R2 was 256 threads / 64x32 warp tile: occ 12.5%, issue 12.2%, tensor
//    28.5% -> issue-latency bound. 16 warps = 4 eligible warps per SMSP.)
//   A: LDG fp32 -> cvt bf16 -> STS (2-stage). B: cp.async (3-stage ring).
// ---------------------------------------------------------------------------
static constexpr int BM = 128, BN = 128, BK = 64;
static constexpr int NC = KDIM / BK;          // 64
static constexpr int THREADS = 512;

static constexpr int A_ST = BM * 128;         // 16 KB (128 rows x 128B)
static constexpr int B_ST = BN * 128;         // 16 KB
static constexpr int B_OFF = 2 * A_ST;        // A double-buffer first
static constexpr int SMEM_TOTAL = B_OFF + 3 * B_ST;  // 80 KB

// Load x tile (fp32) for chunk c into registers, converted to packed bf16x2.
__device__ __forceinline__ void ldgA(const float* __restrict__ xg,
                                     int c, int tid, uint32_t q[2][4]) {
    const float* p0 = xg + (size_t)c * BK;
    #pragma unroll
    for (int it = 0; it < 2; it++) {
        const int task = tid + it * THREADS;      // 0..1023
        const int r = task >> 3;                  // row 0..127
        const int t = task & 7;                   // 16B seg of 128B row
        const float4* p = reinterpret_cast<const float4*>(p0 + (size_t)r * KDIM + t * 8);
        float4 f0 = p[0], f1 = p[1];
        q[it][0] = pack_bf16x2(f0.x, f0.y);
        q[it][1] = pack_bf16x2(f0.z, f0.w);
        q[it][2] = pack_bf16x2(f1.x, f1.y);
        q[it][3] = pack_bf16x2(f1.z, f1.w);
    }
}

__device__ __forceinline__ void stsA(uint32_t abase, int tid, const uint32_t q[2][4]) {
    #pragma unroll
    for (int it = 0; it < 2; it++) {
        const int task = tid + it * THREADS;
        const int r = task >> 3;
        const int t = task & 7;
        const uint32_t dst = abase + SWZ(r * 128 + t * 16);
        STS128(dst, q[it][0], q[it][1], q[it][2], q[it][3]);
    }
}

// cp.async the bf16 weight tile for chunk c into B stage buffer.
__device__ __forceinline__ void cpB(uint32_t bbase, int c, int n0, int tid) {
    const __nv_bfloat16* wg = g_wbin + (size_t)n0 * KDIM + (size_t)c * BK;
    #pragma unroll
    for (int it = 0; it < 2; it++) {
        const int task = tid + it * THREADS;
        const int r = task >> 3;                  // n-row 0..127
        const int t = task & 7;
        const __nv_bfloat16* src = wg + (size_t)r * KDIM + t * 8;
        const uint32_t dst = bbase + SWZ(r * 128 + t * 16);
        CP_ASYNC16(dst, src);
    }
}

__global__ void __launch_bounds__(THREADS, 1) binlin_gemm(
    const float* __restrict__ x, float* __restrict__ out) {
    extern __shared__ char smem[];
    const uint32_t smem_base = smem_u32(smem);
    const int tid = threadIdx.x;
    const int wid = tid >> 5;
    const int lid = tid & 31;

    const int n0 = blockIdx.x * BN;               // 0..383 step 128
    const int m0 = blockIdx.y * BM;               // 0..16256 step 128
    const float* xg = x + (size_t)m0 * KDIM;

    const int warp_m = wid >> 2;                  // 0..3  (32 rows each)
    const int warp_n = wid & 3;                   // 0..3  (32 cols each)

    // per-lane ldmatrix address components
    const int lr = lid & 7;
    const int lg = lid >> 3;
    const int a_row  = warp_m * 32 + (lg & 1) * 8 + lr;   // + mf*16
    const int a_colb = (lg >> 1) * 16;                    // + ks*32
    const int b_row  = warp_n * 32 + (lg >> 1) * 8 + lr;  // + nf2*16
    const int b_colb = (lg & 1) * 16;                     // + ks*32

    float acc[2][4][4];
    #pragma unroll
    for (int i = 0; i < 2; i++)
        #pragma unroll
        for (int j = 0; j < 4; j++)
            #pragma unroll
            for (int k = 0; k < 4; k++) acc[i][j][k] = 0.f;

    uint32_t q[2][4];

    // ---- prologue ----
    cpB(smem_base + B_OFF + 0 * B_ST, 0, n0, tid); CP_COMMIT();
    ldgA(xg, 0, tid, q);
    stsA(smem_base + 0 * A_ST, tid, q);
    cpB(smem_base + B_OFF + 1 * B_ST, 1, n0, tid); CP_COMMIT();
    ldgA(xg, 1, tid, q);                          // q holds A(1)
    asm volatile("cp.async.wait_group 1;" ::: "memory");   // B(0) done
    __syncthreads();

    // ---- main loop ----
    for (int c = 0; c < NC; c++) {
        const int s = c & 1;
        const uint32_t abase = smem_base + s * A_ST;
        const uint32_t bbase = smem_base + B_OFF + (c % 3) * B_ST;

        // stage A(c+1) into the other A buffer (safe: consumed at c-1)
        if (c + 1 < NC) stsA(smem_base + (s ^ 1) * A_ST, tid, q);
        // issue loads for c+2 (B ring stage (c+2)%3 is idle this iter)
        if (c + 2 < NC) {
            cpB(smem_base + B_OFF + ((c + 2) % 3) * B_ST, c + 2, n0, tid);
            ldgA(xg, c + 2, tid, q);
        }
        CP_COMMIT();   // group for B(c+2) (possibly empty near tail)

        // ---- compute chunk c ----
        #pragma unroll
        for (int ks = 0; ks < 4; ks++) {
            uint32_t a[2][4];
            #pragma unroll
            for (int mf = 0; mf < 2; mf++) {
                const uint32_t addr = abase +
                    SWZ((a_row + mf * 16) * 128 + ks * 32 + a_colb);
                LDSM_X4(a[mf][0], a[mf][1], a[mf][2], a[mf][3], addr);
            }
            uint32_t b[2][4];
            #pragma unroll
            for (int nf2 = 0; nf2 < 2; nf2++) {
                const uint32_t addr = bbase +
                    SWZ((b_row + nf2 * 16) * 128 + ks * 32 + b_colb);
                LDSM_X4(b[nf2][0], b[nf2][1], b[nf2][2], b[nf2][3], addr);
            }
            #pragma unroll
            for (int mf = 0; mf < 2; mf++) {
                #pragma unroll
                for (int nf = 0; nf < 4; nf++) {
                    MMA16816(acc[mf][nf], a[mf],
                             b[nf >> 1][(nf & 1) * 2 + 0],
                             b[nf >> 1][(nf & 1) * 2 + 1]);
                }
            }
        }

        CP_WAIT1();        // B(c+1) complete
        __syncthreads();
    }

    // ---- epilogue: fragments -> gmem ----
    const int er = lid >> 2;          // 0..7
    const int ec = (lid & 3) * 2;     // 0,2,4,6
    #pragma unroll
    for (int mf = 0; mf < 2; mf++) {
        #pragma unroll
        for (int nf = 0; nf < 4; nf++) {
            const int m = m0 + warp_m * 32 + mf * 16 + er;
            const int n = n0 + warp_n * 32 + nf * 8 + ec;
            float2 v0 = make_float2(acc[mf][nf][0], acc[mf][nf][1]);
            float2 v1 = make_float2(acc[mf][nf][2], acc[mf][nf][3]);
            *reinterpret_cast<float2*>(out + (size_t)m * NDIM + n)       = v0;
            *reinterpret_cast<float2*>(out + (size_t)(m + 8) * NDIM + n) = v1;
        }
    }
}

// ---------------------------------------------------------------------------
// Launch
// ---------------------------------------------------------------------------
extern "C" void kernel_launch(void* const* d_in, const int* in_sizes, int n_in,
                              void* d_out, int out_size) {
    const float* x = (const float*)d_in[0];   // [16384, 4096]
    const float* w = (const float*)d_in[1];   // [512, 4096] bernoulli probs
    const float* u = (const float*)d_in[2];   // [512, 4096] uniform sample
    float* out = (float*)d_out;               // [16384, 512]

    cudaFuncSetAttribute(binlin_gemm,
                         cudaFuncAttributeMaxDynamicSharedMemorySize, SMEM_TOTAL);

    binarize_kernel<<<(NDIM * KDIM) / (256 * 8), 256>>>(w, u);
    dim3 grid(NDIM / BN, BDIM / BM);          // (4, 128)
    binlin_gemm<<<grid, THREADS, SMEM_TOTAL>>>(x, out);
}

// round 4
// speedup vs baseline: 1.7491x; 1.7491x over previous
#include <cuda_runtime.h>
#include <cuda_bf16.h>
#include <cstdint>
#include <cstring>

// Problem dims
#define BDIM 16384
#define KDIM 4096
#define NDIM 512

// Binarized weight, bf16 {0,1}, [NDIM, KDIM] row-major (K-contiguous). 4 MB.
__device__ __align__(256) __nv_bfloat16 g_wbin[(size_t)NDIM * KDIM];
// Pre-converted x, bf16, [BDIM, KDIM]. 128 MB.
__device__ __align__(256) __nv_bfloat16 g_xbf[(size_t)BDIM * KDIM];

// ---------------------------------------------------------------------------
// helpers
// ---------------------------------------------------------------------------
__device__ __forceinline__ uint32_t smem_u32(const void* p) {
    uint32_t a;
    asm("{ .reg .u64 t; cvta.to.shared.u64 t, %1; cvt.u32.u64 %0, t; }"
        : "=r"(a) : "l"(p));
    return a;
}

#define SWZ(off) ((uint32_t)(off) ^ ((((uint32_t)(off)) >> 3) & 0x70))

#define LDSM_X4(r0, r1, r2, r3, addr) \
    asm volatile("ldmatrix.sync.aligned.m8n8.x4.shared.b16 {%0,%1,%2,%3}, [%4];" \
        : "=r"(r0), "=r"(r1), "=r"(r2), "=r"(r3) : "r"(addr))

#define MMA16816(d, a, b0, b1) \
    asm volatile("mma.sync.aligned.m16n8k16.row.col.f32.bf16.bf16.f32 " \
        "{%0,%1,%2,%3}, {%4,%5,%6,%7}, {%8,%9}, {%0,%1,%2,%3};" \
        : "+f"((d)[0]), "+f"((d)[1]), "+f"((d)[2]), "+f"((d)[3]) \
        : "r"((a)[0]), "r"((a)[1]), "r"((a)[2]), "r"((a)[3]), "r"(b0), "r"(b1))

#define CP_ASYNC16(dst, src) \
    asm volatile("cp.async.cg.shared.global [%0], [%1], 16;" \
        :: "r"(dst), "l"(src) : "memory")
#define CP_COMMIT() asm volatile("cp.async.commit_group;" ::: "memory")
#define CP_WAIT2()  asm volatile("cp.async.wait_group 2;" ::: "memory")

__device__ __forceinline__ uint32_t pack_bf16x2(float lo, float hi) {
    __nv_bfloat162 h = __floats2bfloat162_rn(lo, hi);
    uint32_t r;
    memcpy(&r, &h, 4);
    return r;
}

// ---------------------------------------------------------------------------
// Kernel 1: binarize weight -> bf16 {0,1}. Pure bit select, no float math.
// ---------------------------------------------------------------------------
__global__ void __launch_bounds__(256) binarize_kernel(
    const float* __restrict__ w, const float* __restrict__ u) {
    int i = blockIdx.x * 256 + threadIdx.x;   // 8 elems each
    const float4* w4 = reinterpret_cast<const float4*>(w) + (size_t)i * 2;
    const float4* u4 = reinterpret_cast<const float4*>(u) + (size_t)i * 2;
    float4 wa = w4[0], wb = w4[1];
    float4 ua = u4[0], ub = u4[1];
    // bf16(1.0f) = 0x3F80
    uint32_t o0 = (ua.x < wa.x ? 0x00003F80u : 0u) | (ua.y < wa.y ? 0x3F800000u : 0u);
    uint32_t o1 = (ua.z < wa.z ? 0x00003F80u : 0u) | (ua.w < wa.w ? 0x3F800000u : 0u);
    uint32_t o2 = (ub.x < wb.x ? 0x00003F80u : 0u) | (ub.y < wb.y ? 0x3F800000u : 0u);
    uint32_t o3 = (ub.z < wb.z ? 0x00003F80u : 0u) | (ub.w < wb.w ? 0x3F800000u : 0u);
    reinterpret_cast<uint4*>(g_wbin)[i] = make_uint4(o0, o1, o2, o3);
}

// ---------------------------------------------------------------------------
// Kernel 2: convert x fp32 -> bf16 (streaming, DRAM-bound ~60us).
// Removes the LDG->cvt->STS chain from the GEMM critical path entirely.
// ---------------------------------------------------------------------------
__global__ void __launch_bounds__(256) convert_x_kernel(const float* __restrict__ x) {
    int i = blockIdx.x * 256 + threadIdx.x;   // 8 elems each
    const float4* p = reinterpret_cast<const float4*>(x) + (size_t)i * 2;
    float4 f0 = p[0], f1 = p[1];
    uint4 o;
    o.x = pack_bf16x2(f0.x, f0.y);
    o.y = pack_bf16x2(f0.z, f0.w);
    o.z = pack_bf16x2(f1.x, f1.y);
    o.w = pack_bf16x2(f1.z, f1.w);
    reinterpret_cast<uint4*>(g_xbf)[i] = o;
}

// ---------------------------------------------------------------------------
// Kernel 3: bf16 mma.sync GEMM, all-cp.async, 4-stage pipeline.
//   out[16384, 512] = g_xbf[16384, 4096] @ g_wbin[512, 4096]^T
//   BM=256, BN=128, BK=64. 256 threads = 8 warps (4 x 2), warp tile 64x64.
//   (R2/R3: tensor ~28% with 1800cyc/chunk of LDG-chain + sync exposure.
//    Now: no register staging, deep async pipeline, 2x FLOP per LDS byte.)
// ---------------------------------------------------------------------------
static constexpr int BM = 256, BN = 128, BK = 64;
static constexpr int NC = KDIM / BK;              // 64
static constexpr int THREADS = 256;
static constexpr int STAGES = 4;

static constexpr int A_ST  = BM * 128;            // 32 KB
static constexpr int B_ST  = BN * 128;            // 16 KB
static constexpr int STAGE = A_ST + B_ST;         // 48 KB
static constexpr int SMEM_TOTAL = STAGES * STAGE; // 192 KB

// cp.async both tiles for chunk c into stage buffer.
__device__ __forceinline__ void cpAB(uint32_t sbase, int c, int m0, int n0, int tid) {
    const __nv_bfloat16* ag = g_xbf + (size_t)m0 * KDIM + (size_t)c * BK;
    #pragma unroll
    for (int it = 0; it < 8; it++) {              // 2048 tasks: 256 rows x 8 segs
        const int task = tid + it * THREADS;
        const int r = task >> 3;
        const int t = task & 7;
        CP_ASYNC16(sbase + SWZ(r * 128 + t * 16),
                   ag + (size_t)r * KDIM + t * 8);
    }
    const __nv_bfloat16* bg = g_wbin + (size_t)n0 * KDIM + (size_t)c * BK;
    const uint32_t bbase = sbase + A_ST;
    #pragma unroll
    for (int it = 0; it < 4; it++) {              // 1024 tasks: 128 rows x 8 segs
        const int task = tid + it * THREADS;
        const int r = task >> 3;
        const int t = task & 7;
        CP_ASYNC16(bbase + SWZ(r * 128 + t * 16),
                   bg + (size_t)r * KDIM + t * 8);
    }
}

__global__ void __launch_bounds__(THREADS, 1) binlin_gemm(float* __restrict__ out) {
    extern __shared__ char smem[];
    const uint32_t smem_base = smem_u32(smem);
    const int tid = threadIdx.x;
    const int wid = tid >> 5;
    const int lid = tid & 31;

    const int n0 = blockIdx.x * BN;               // 0..384 step 128
    const int m0 = blockIdx.y * BM;               // 0..16128 step 256

    const int warp_m = wid >> 1;                  // 0..3  (64 rows each)
    const int warp_n = wid & 1;                   // 0..1  (64 cols each)

    // per-lane ldmatrix address components
    const int lr = lid & 7;
    const int lg = lid >> 3;
    const int a_row  = warp_m * 64 + (lg & 1) * 8 + lr;   // + mf*16
    const int a_colb = (lg >> 1) * 16;                    // + ks*32
    const int b_row  = warp_n * 64 + (lg >> 1) * 8 + lr;  // + nf2*16
    const int b_colb = (lg & 1) * 16;                     // + ks*32

    float acc[4][8][4];
    #pragma unroll
    for (int i = 0; i < 4; i++)
        #pragma unroll
        for (int j = 0; j < 8; j++)
            #pragma unroll
            for (int k = 0; k < 4; k++) acc[i][j][k] = 0.f;

    // ---- prologue: prefetch stages 0..2 ----
    #pragma unroll
    for (int s = 0; s < STAGES - 1; s++) {
        cpAB(smem_base + s * STAGE, s, m0, n0, tid);
        CP_COMMIT();
    }

    // ---- main loop ----
    for (int c = 0; c < NC; c++) {
        CP_WAIT2();            // 3 groups pending -> oldest (chunk c) complete
        __syncthreads();       // visibility + stage (c+3)&3 free of readers

        if (c + STAGES - 1 < NC)
            cpAB(smem_base + ((c + STAGES - 1) & 3) * STAGE, c + STAGES - 1, m0, n0, tid);
        CP_COMMIT();           // keep group count in lockstep (may be empty)

        const uint32_t abase = smem_base + (c & 3) * STAGE;
        const uint32_t bbase = abase + A_ST;

        #pragma unroll
        for (int ks = 0; ks < 4; ks++) {
            uint32_t a[4][4];
            #pragma unroll
            for (int mf = 0; mf < 4; mf++) {
                const uint32_t addr = abase +
                    SWZ((a_row + mf * 16) * 128 + ks * 32 + a_colb);
                LDSM_X4(a[mf][0], a[mf][1], a[mf][2], a[mf][3], addr);
            }
            uint32_t b[4][4];
            #pragma unroll
            for (int nf2 = 0; nf2 < 4; nf2++) {
                const uint32_t addr = bbase +
                    SWZ((b_row + nf2 * 16) * 128 + ks * 32 + b_colb);
                LDSM_X4(b[nf2][0], b[nf2][1], b[nf2][2], b[nf2][3], addr);
            }
            #pragma unroll
            for (int mf = 0; mf < 4; mf++) {
                #pragma unroll
                for (int nf = 0; nf < 8; nf++) {
                    MMA16816(acc[mf][nf], a[mf],
                             b[nf >> 1][(nf & 1) * 2 + 0],
                             b[nf >> 1][(nf & 1) * 2 + 1]);
                }
            }
        }
    }

    // ---- epilogue: fragments -> gmem ----
    const int er = lid >> 2;          // 0..7
    const int ec = (lid & 3) * 2;     // 0,2,4,6
    #pragma unroll
    for (int mf = 0; mf < 4; mf++) {
        #pragma unroll
        for (int nf = 0; nf < 8; nf++) {
            const int m = m0 + warp_m * 64 + mf * 16 + er;
            const int n = n0 + warp_n * 64 + nf * 8 + ec;
            float2 v0 = make_float2(acc[mf][nf][0], acc[mf][nf][1]);
            float2 v1 = make_float2(acc[mf][nf][2], acc[mf][nf][3]);
            *reinterpret_cast<float2*>(out + (size_t)m * NDIM + n)       = v0;
            *reinterpret_cast<float2*>(out + (size_t)(m + 8) * NDIM + n) = v1;
        }
    }
}

// ---------------------------------------------------------------------------
// Launch
// ---------------------------------------------------------------------------
extern "C" void kernel_launch(void* const* d_in, const int* in_sizes, int n_in,
                              void* d_out, int out_size) {
    const float* x = (const float*)d_in[0];   // [16384, 4096]
    const float* w = (const float*)d_in[1];   // [512, 4096] bernoulli probs
    const float* u = (const float*)d_in[2];   // [512, 4096] uniform sample
    float* out = (float*)d_out;               // [16384, 512]

    cudaFuncSetAttribute(binlin_gemm,
                         cudaFuncAttributeMaxDynamicSharedMemorySize, SMEM_TOTAL);

    binarize_kernel<<<(NDIM * KDIM) / (256 * 8), 256>>>(w, u);
    convert_x_kernel<<<((size_t)BDIM * KDIM) / (256 * 8), 256>>>(x);
    dim3 grid(NDIM / BN, BDIM / BM);          // (4, 64) = 256 CTAs
    binlin_gemm<<<grid, THREADS, SMEM_TOTAL>>>(out);
}